// round 10
// baseline (speedup 1.0000x reference)
#include <cuda_runtime.h>
#include <cuda_fp16.h>
#include <cstdint>

// ---------------------------------------------------------------------------
// GraphNeuralNetwork: 4 sparse layers, DEG=64 parents per node, B=512.
// Round 10: R9 inner loop (FFMA2) + 2 CTAs/SM for the wide layers via
// WCHUNK=128 / NCH=16 (NPC stays 64 -> fill traffic unchanged, grid 128).
// fp16 staging, fp32 weights + accumulation.
// ---------------------------------------------------------------------------

#define BATCH    512
#define THREADS  1024
#define ESTRIDE  80         // padded edge slots per node (64 + <=16 fillers, even)

// wide kernel (layers 0-2)
#define WCOLS    128
#define WCHUNK   128        // 128 rows x 128 cols fp16 = 32KB per buffer
#define WNPC     64
#define WNPW     2          // 32 warps, 2 nodes each

// narrow kernel (layer 3)
#define NCOLS    64
#define NCHUNK3  4
#define NCHUNKSZ 512        // 512 rows x 64 cols fp16 = 64KB
#define NNPC     32         // 32 warps, 1 node each; 2 CTAs/SM

__device__ __align__(16) __half g_hA[2048 * 512];
__device__ __align__(16) __half g_hB[2048 * 512];
__device__ __align__(16) int2   g_edges[4][2048 * ESTRIDE]; // {chunk byte off, w bits}
__device__ int                  g_cnt[4][2048 * 16];        // per (node,bucket) padded counts

// ---------------------------------------------------------------------------
// Prep: warp-per-node stable partition of 64 edges into NB buckets, each
// padded to even count with {0, 0.0f} fillers.
// Wide: bucket = s>>7 (128-row chunks), byteoff = (s&127)*256.
// Narrow: bucket = s>>9 (512-row chunks), byteoff = (s&511)*128.
// ---------------------------------------------------------------------------
template <int NB, int BSHIFT, int OSHIFT>
__device__ __forceinline__ void prep_node_warp(
    const int* __restrict__ src, const float* __restrict__ w,
    int gw, int lane, int2* __restrict__ ed, int* __restrict__ cnt) {
    int base = gw * ESTRIDE;

    int   s0 = src[gw * 64 + lane];       int   s1 = src[gw * 64 + 32 + lane];
    float v0 = w[gw * 64 + lane];         float v1 = w[gw * 64 + 32 + lane];
    int   c0 = s0 >> BSHIFT,              c1 = s1 >> BSHIFT;
    const int MASK = (1 << BSHIFT) - 1;

    unsigned m0[NB], m1[NB];
#pragma unroll
    for (int c = 0; c < NB; c++) {
        m0[c] = __ballot_sync(0xffffffffu, c0 == c);
        m1[c] = __ballot_sync(0xffffffffu, c1 == c);
    }
    int cntc[NB], pc[NB], off[NB]; int run = 0;
#pragma unroll
    for (int c = 0; c < NB; c++) {
        cntc[c] = __popc(m0[c]) + __popc(m1[c]);
        pc[c]   = (cntc[c] + 1) & ~1;        // pad to even
        off[c]  = run; run += pc[c];
    }

    unsigned lt = (1u << lane) - 1u;
    int p0 = off[c0] + __popc(m0[c0] & lt);
    int p1 = off[c1] + __popc(m0[c1]) + __popc(m1[c1] & lt);

    ed[base + p0] = make_int2((s0 & MASK) << OSHIFT, __float_as_int(v0));
    ed[base + p1] = make_int2((s1 & MASK) << OSHIFT, __float_as_int(v1));
    if (lane < NB) {
        if (cntc[lane] & 1)
            ed[base + off[lane] + cntc[lane]] = make_int2(0, 0);  // zero-weight filler
        cnt[(gw << 4) + lane] = pc[lane];
    }
}

__global__ void fused_prep(
    const float* __restrict__ x, __half* __restrict__ hA,
    const int* __restrict__ src0, const float* __restrict__ w0,
    const int* __restrict__ src1, const float* __restrict__ w1,
    const int* __restrict__ src2, const float* __restrict__ w2,
    const int* __restrict__ src3, const float* __restrict__ w3,
    int2* __restrict__ ed, int* __restrict__ cnt) {
    __shared__ float t[32][33];
    int b   = blockIdx.x;
    int tid = threadIdx.x;

    if (b < 256) {
        // transpose x [512,512] fp32 -> hA [node, batch] fp16
        int bx = (b & 15) * 32, by = (b >> 4) * 32;
        int tx = tid & 31, ty = tid >> 5;       // 32 x 8
#pragma unroll
        for (int i = 0; i < 32; i += 8)
            t[ty + i][tx] = x[(by + ty + i) * 512 + bx + tx];
        __syncthreads();
#pragma unroll
        for (int i = 0; i < 32; i += 8)
            hA[(bx + ty + i) * 512 + by + tx] = __float2half(t[tx][ty + i]);
        return;
    }

    int lane = tid & 31;
    int warp = tid >> 5;                        // 8 warps/block
    int pb   = b - 256;
    if (pb < 256) {          // layer 0: n_prev=512 -> 4 buckets of 128 rows
        prep_node_warp<4, 7, 8>(src0, w0, pb * 8 + warp, lane, ed, cnt);
    } else if (pb < 512) {   // layer 1: 16 buckets of 128 rows
        prep_node_warp<16, 7, 8>(src1, w1, (pb - 256) * 8 + warp, lane,
                                 ed + 1 * 2048 * ESTRIDE, cnt + 1 * 32768);
    } else if (pb < 768) {   // layer 2
        prep_node_warp<16, 7, 8>(src2, w2, (pb - 512) * 8 + warp, lane,
                                 ed + 2 * 2048 * ESTRIDE, cnt + 2 * 32768);
    } else {                 // layer 3: narrow (4 buckets of 512 rows, COLS=64)
        prep_node_warp<4, 9, 7>(src3, w3, (pb - 768) * 8 + warp, lane,
                                ed + 3 * 2048 * ESTRIDE, cnt + 3 * 32768);
    }
}

// ---------------------------------------------------------------------------
// cp.async helpers
// ---------------------------------------------------------------------------
__device__ __forceinline__ void cp16(unsigned dst, const void* src) {
    asm volatile("cp.async.cg.shared.global [%0], [%1], 16;" :: "r"(dst), "l"(src));
}
__device__ __forceinline__ void cp_commit() {
    asm volatile("cp.async.commit_group;");
}
template <int N>
__device__ __forceinline__ void cp_wait() {
    asm volatile("cp.async.wait_group %0;" :: "n"(N) : "memory");
}
__device__ __forceinline__ unsigned smem_u32(const void* p) {
    unsigned r;
    asm("{ .reg .u64 t; cvta.to.shared.u64 t, %1; cvt.u32.u64 %0, t; }"
        : "=r"(r) : "l"(p));
    return r;
}

// ---------------------------------------------------------------------------
// Wide layer kernel (layers 0-2). CTA: 128 batch cols x 64 nodes, 1024 thr,
// 2 CTAs/SM. Warp = 1 node x 128 cols (4 fp16/lane). Double-buffered 32KB
// chunks (128 rows) + 40KB staged edges. FFMA2 MACs.
// ---------------------------------------------------------------------------
template <int NCH>
__global__ __launch_bounds__(THREADS, 2)
void layer_wide(const __half* __restrict__ h_in,
                const int2*  __restrict__ gedges,
                const int*   __restrict__ gcnt,
                const float* __restrict__ bias,
                __half*      __restrict__ out) {
    extern __shared__ __align__(16) char smem[];
    __half* sh0 = (__half*)smem;                             // buffer 0 (32KB)
    __half* sh1 = (__half*)(smem + WCHUNK * WCOLS * 2);      // buffer 1 (32KB)
    int4*   se  = (int4*)(smem + 2 * WCHUNK * WCOLS * 2);    // edges (40KB)
    __shared__ int so[WNPC][NCH + 1];

    const int tid  = threadIdx.x;
    const int lane = tid & 31, warp = tid >> 5;
    const int ct0      = blockIdx.x * WCOLS;
    const int nodeBase = blockIdx.y * WNPC;

    if (tid < WNPC) {
        int r = 0;
#pragma unroll
        for (int c = 0; c < NCH; c++) {
            so[tid][c] = r;
            r += gcnt[(nodeBase + tid) * 16 + c];
        }
        so[tid][NCH] = r;
    }

    unsigned b0u = smem_u32(sh0), b1u = smem_u32(sh1), seu = smem_u32(se);

    // group 0: edges + chunk 0
    {
        const int4* gsr = (const int4*)(gedges + (size_t)nodeBase * ESTRIDE);
#pragma unroll
        for (int i = tid; i < WNPC * ESTRIDE / 2; i += THREADS)
            cp16(seu + i * 16, gsr + i);
        const __half* gsrc = h_in + ct0;
#pragma unroll
        for (int i = tid; i < WCHUNK * (WCOLS / 8); i += THREADS) {
            int row = i >> 4, q = i & 15;       // 16 x 16B per 256B row
            cp16(b0u + i * 16, gsrc + row * BATCH + q * 8);
        }
        cp_commit();
    }

    // accumulators: packed f32x2 pairs (cols lane*4+{0,1} and +{2,3}) per node
    unsigned long long accA[WNPW], accB[WNPW];
#pragma unroll
    for (int i = 0; i < WNPW; i++) { accA[i] = 0ull; accB[i] = 0ull; }

    for (int c = 0; c < NCH; c++) {
        // prefetch chunk c+1 into the other buffer (safe: gathers of c-1 synced)
        if (c + 1 < NCH) {
            unsigned dbu = ((c + 1) & 1) ? b1u : b0u;
            const __half* gsrc = h_in + (size_t)(c + 1) * WCHUNK * BATCH + ct0;
#pragma unroll
            for (int i = tid; i < WCHUNK * (WCOLS / 8); i += THREADS) {
                int row = i >> 4, q = i & 15;
                cp16(dbu + i * 16, gsrc + row * BATCH + q * 8);
            }
        }
        cp_commit();
        cp_wait<1>();          // chunk c (and edges) landed
        __syncthreads();

        const __half* buf = (c & 1) ? sh1 : sh0;
        const char*   shb = (const char*)buf + lane * 8;   // 4 fp16 cols per lane

#pragma unroll
        for (int i = 0; i < WNPW; i++) {
            int n  = warp * WNPW + i;
            int k0 = so[n][c] >> 1;             // pair index (counts are even)
            int k1 = so[n][c + 1] >> 1;
            const int4* ep = se + n * (ESTRIDE / 2);
            unsigned long long aA = accA[i], aB = accB[i];
#pragma unroll 2
            for (int k = k0; k < k1; k++) {
                int4 e = ep[k];                 // LDS.128 broadcast, 2 edges
                uint2 g0 = *(const uint2*)(shb + e.x);
                uint2 g1 = *(const uint2*)(shb + e.z);
                unsigned long long w0p, w1p;
                asm("mov.b64 %0, {%1, %1};" : "=l"(w0p) : "r"(e.y));
                asm("mov.b64 %0, {%1, %1};" : "=l"(w1p) : "r"(e.w));
                float2 f0a = __half22float2(*(__half2*)&g0.x);
                float2 f0b = __half22float2(*(__half2*)&g0.y);
                float2 f1a = __half22float2(*(__half2*)&g1.x);
                float2 f1b = __half22float2(*(__half2*)&g1.y);
                unsigned long long p0a, p0b, p1a, p1b;
                asm("mov.b64 %0, {%1, %2};" : "=l"(p0a) : "f"(f0a.x), "f"(f0a.y));
                asm("mov.b64 %0, {%1, %2};" : "=l"(p0b) : "f"(f0b.x), "f"(f0b.y));
                asm("mov.b64 %0, {%1, %2};" : "=l"(p1a) : "f"(f1a.x), "f"(f1a.y));
                asm("mov.b64 %0, {%1, %2};" : "=l"(p1b) : "f"(f1b.x), "f"(f1b.y));
                asm("fma.rn.f32x2 %0, %1, %2, %0;" : "+l"(aA) : "l"(p0a), "l"(w0p));
                asm("fma.rn.f32x2 %0, %1, %2, %0;" : "+l"(aB) : "l"(p0b), "l"(w0p));
                asm("fma.rn.f32x2 %0, %1, %2, %0;" : "+l"(aA) : "l"(p1a), "l"(w1p));
                asm("fma.rn.f32x2 %0, %1, %2, %0;" : "+l"(aB) : "l"(p1b), "l"(w1p));
            }
            accA[i] = aA; accB[i] = aB;
        }
        __syncthreads();       // gathers done before next prefetch overwrites
    }

#pragma unroll
    for (int i = 0; i < WNPW; i++) {
        int n = warp * WNPW + i;
        int j = nodeBase + n;
        float bv = bias[j];
        float v0 = fmaxf(__uint_as_float((unsigned)(accA[i]       )) + bv, 0.f);
        float v1 = fmaxf(__uint_as_float((unsigned)(accA[i] >> 32 )) + bv, 0.f);
        float v2 = fmaxf(__uint_as_float((unsigned)(accB[i]       )) + bv, 0.f);
        float v3 = fmaxf(__uint_as_float((unsigned)(accB[i] >> 32 )) + bv, 0.f);
        __half2 h0 = __floats2half2_rn(v0, v1);
        __half2 h1 = __floats2half2_rn(v2, v3);
        uint2 pk = make_uint2(*(unsigned*)&h0, *(unsigned*)&h1);
        *(uint2*)(out + (size_t)j * BATCH + ct0 + lane * 4) = pk;
    }
}

// ---------------------------------------------------------------------------
// Narrow layer kernel (final layer). COLS=64, CHUNK=512, 4 buckets,
// NPC=32 (2 CTAs/SM, 128 CTAs). Writes d_out [B, 512] fp32.
// ---------------------------------------------------------------------------
__global__ __launch_bounds__(THREADS, 2)
void layer_final(const __half* __restrict__ h_in,
                 const int2*  __restrict__ gedges,
                 const int*   __restrict__ gcnt,
                 const float* __restrict__ bias,
                 float*       __restrict__ out) {
    extern __shared__ __align__(16) char smem[];
    __half* sh = (__half*)smem;                          // 64KB chunk
    int4*   se = (int4*)(smem + NCHUNKSZ * NCOLS * 2);   // 20KB edges
    __shared__ int so[NNPC][NCHUNK3 + 1];

    const int tid  = threadIdx.x;
    const int lane = tid & 31, warp = tid >> 5;
    const int ct0      = blockIdx.x * NCOLS;
    const int nodeBase = blockIdx.y * NNPC;

    if (tid < NNPC) {
        int r = 0;
#pragma unroll
        for (int c = 0; c < NCHUNK3; c++) {
            so[tid][c] = r;
            r += gcnt[(nodeBase + tid) * 16 + c];
        }
        so[tid][NCHUNK3] = r;
    }

    unsigned shu = smem_u32(sh), seu = smem_u32(se);
    const char* shb = (const char*)sh + lane * 4;   // 2 fp16 cols per lane

    {
        const int4* gsr = (const int4*)(gedges + (size_t)nodeBase * ESTRIDE);
#pragma unroll
        for (int i = tid; i < NNPC * ESTRIDE / 2; i += THREADS)
            cp16(seu + i * 16, gsr + i);
    }

    float2 acc = make_float2(0.f, 0.f);
    const int  n  = warp;                       // 1 node per warp
    const int4* ep = se + n * (ESTRIDE / 2);

    for (int c = 0; c < NCHUNK3; c++) {
        __syncthreads();
        const __half* gsrc = h_in + (size_t)c * NCHUNKSZ * BATCH + ct0;
#pragma unroll
        for (int i = tid; i < NCHUNKSZ * (NCOLS / 8); i += THREADS) {
            int row = i >> 3, q = i & 7;
            cp16(shu + i * 16, gsrc + row * BATCH + q * 8);
        }
        cp_commit();
        cp_wait<0>();
        __syncthreads();

        int k0 = so[n][c] >> 1;
        int k1 = so[n][c + 1] >> 1;
#pragma unroll 2
        for (int k = k0; k < k1; k++) {
            int4 e = ep[k];
            __half2 h0 = *(const __half2*)(shb + e.x);
            __half2 h1 = *(const __half2*)(shb + e.z);
            float w0 = __int_as_float(e.y);
            float w1 = __int_as_float(e.w);
            float2 f0 = __half22float2(h0);
            float2 f1 = __half22float2(h1);
            acc.x = fmaf(f0.x, w0, acc.x);
            acc.y = fmaf(f0.y, w0, acc.y);
            acc.x = fmaf(f1.x, w1, acc.x);
            acc.y = fmaf(f1.y, w1, acc.y);
        }
    }

    {
        int j = nodeBase + n;
        float bv = bias[j];
        float vx = acc.x + bv;
        float vy = acc.y + bv;
        int cidx = ct0 + lane * 2;              // d_out [B, 512] row-major
        out[(size_t)cidx * 512 + j]       = vx;
        out[(size_t)(cidx + 1) * 512 + j] = vy;
    }
}

// ---------------------------------------------------------------------------
// Host launch
// ---------------------------------------------------------------------------
extern "C" void kernel_launch(void* const* d_in, const int* in_sizes, int n_in,
                              void* d_out, int out_size) {
    (void)n_in; (void)out_size;

    const float* x;
    const float* w[4];
    const float* b[4];
    const int*   src[4];

    if (in_sizes[0] == 2048) {
        // alphabetical metadata order: b0..b3, dst0..dst3, src0..src3, w0..w3, x
        for (int l = 0; l < 4; l++) {
            b[l]   = (const float*)d_in[l];
            src[l] = (const int*)d_in[8 + l];
            w[l]   = (const float*)d_in[12 + l];
        }
        x = (const float*)d_in[16];
    } else if (in_sizes[7] == 32768) {
        // reference-signature order: x, w0,b0, ..., w3,b3, src0,dst0, ...
        x = (const float*)d_in[0];
        for (int l = 0; l < 4; l++) {
            w[l]   = (const float*)d_in[1 + 2 * l];
            b[l]   = (const float*)d_in[2 + 2 * l];
            src[l] = (const int*)d_in[9 + 2 * l];
        }
    } else {
        // setup_inputs dict order: x, (w,b,src,dst) per layer
        x = (const float*)d_in[0];
        for (int l = 0; l < 4; l++) {
            w[l]   = (const float*)d_in[1 + 4 * l];
            b[l]   = (const float*)d_in[2 + 4 * l];
            src[l] = (const int*)d_in[3 + 4 * l];
        }
    }

    __half* hA; __half* hB; int2* ed; int* cnt;
    cudaGetSymbolAddress((void**)&hA,  g_hA);
    cudaGetSymbolAddress((void**)&hB,  g_hB);
    cudaGetSymbolAddress((void**)&ed,  g_edges);
    cudaGetSymbolAddress((void**)&cnt, g_cnt);

    constexpr int SMEM_WIDE  = 2 * WCHUNK * WCOLS * 2 + WNPC * ESTRIDE * 8; // 106496
    constexpr int SMEM_FINAL = NCHUNKSZ * NCOLS * 2 + NNPC * ESTRIDE * 8;   // 86016

    cudaFuncSetAttribute(layer_wide<4>,
                         cudaFuncAttributeMaxDynamicSharedMemorySize, SMEM_WIDE);
    cudaFuncSetAttribute(layer_wide<16>,
                         cudaFuncAttributeMaxDynamicSharedMemorySize, SMEM_WIDE);
    cudaFuncSetAttribute(layer_final,
                         cudaFuncAttributeMaxDynamicSharedMemorySize, SMEM_FINAL);

    // 1) fused: transpose x -> hA (fp16)  +  partition all 4 layers' edges
    fused_prep<<<1088, 256>>>(x, hA,
                              src[0], w[0], src[1], w[1],
                              src[2], w[2], src[3], w[3],
                              ed, cnt);

    // 2) layers (n_prev: 512, 2048, 2048, 2048)
    layer_wide<4><<<dim3(4, 32), THREADS, SMEM_WIDE>>>(
        hA, ed + 0 * 2048 * ESTRIDE, cnt + 0 * 32768, b[0], hB);
    layer_wide<16><<<dim3(4, 32), THREADS, SMEM_WIDE>>>(
        hB, ed + 1 * 2048 * ESTRIDE, cnt + 1 * 32768, b[1], hA);
    layer_wide<16><<<dim3(4, 32), THREADS, SMEM_WIDE>>>(
        hA, ed + 2 * 2048 * ESTRIDE, cnt + 2 * 32768, b[2], hB);
    layer_final<<<dim3(8, 16), THREADS, SMEM_FINAL>>>(
        hB, ed + 3 * 2048 * ESTRIDE, cnt + 3 * 32768, b[3], (float*)d_out);
}

// round 11
// speedup vs baseline: 1.5667x; 1.5667x over previous
#include <cuda_runtime.h>
#include <cuda_fp16.h>
#include <cstdint>

// ---------------------------------------------------------------------------
// GraphNeuralNetwork: 4 sparse layers, DEG=64 parents per node, B=512.
// Round 11: direct-L2 gather. h kept as fp16 [node, batch]; a warp owns
// (node, 256-col group) and gathers each source row with one coalesced
// LDG.128 (512B/warp) straight from L2. No SMEM staging, no barriers,
// no buckets. fp32 weights + accumulation.
// ---------------------------------------------------------------------------

#define BATCH 512

__device__ __align__(16) __half g_hA[2048 * 512];
__device__ __align__(16) __half g_hB[2048 * 512];
__device__ __align__(16) int4   g_pairs[4][2048 * 32];  // {off0, w0, off1, w1} per edge pair

// ---------------------------------------------------------------------------
// Fused prep: transpose x (blocks 0..255) + pack edge pairs for all layers
// (blocks 256..1087). Pair k of node n = edges 2k, 2k+1 in natural order;
// offset = src * 1024 (byte offset of row in fp16 [node,batch] buffer).
// ---------------------------------------------------------------------------
__device__ __forceinline__ void prep_node_pairs(
    const int* __restrict__ src, const float* __restrict__ w,
    int gw, int lane, int4* __restrict__ ed) {
    int i0 = gw * 64 + 2 * lane;
    int   s0 = src[i0],     s1 = src[i0 + 1];
    float v0 = w[i0];       float v1 = w[i0 + 1];
    ed[gw * 32 + lane] = make_int4(s0 << 10, __float_as_int(v0),
                                   s1 << 10, __float_as_int(v1));
}

__global__ void fused_prep(
    const float* __restrict__ x, __half* __restrict__ hA,
    const int* __restrict__ src0, const float* __restrict__ w0,
    const int* __restrict__ src1, const float* __restrict__ w1,
    const int* __restrict__ src2, const float* __restrict__ w2,
    const int* __restrict__ src3, const float* __restrict__ w3,
    int4* __restrict__ ed) {
    __shared__ float t[32][33];
    int b   = blockIdx.x;
    int tid = threadIdx.x;

    if (b < 256) {
        // transpose x [512,512] fp32 -> hA [node, batch] fp16
        int bx = (b & 15) * 32, by = (b >> 4) * 32;
        int tx = tid & 31, ty = tid >> 5;       // 32 x 8
#pragma unroll
        for (int i = 0; i < 32; i += 8)
            t[ty + i][tx] = x[(by + ty + i) * 512 + bx + tx];
        __syncthreads();
#pragma unroll
        for (int i = 0; i < 32; i += 8)
            hA[(bx + ty + i) * 512 + by + tx] = __float2half(t[tx][ty + i]);
        return;
    }

    int lane = tid & 31;
    int warp = tid >> 5;                        // 8 warps/block -> 8 nodes/block
    int pb   = b - 256;
    if (pb < 256) {
        prep_node_pairs(src0, w0, pb * 8 + warp, lane, ed);
    } else if (pb < 512) {
        prep_node_pairs(src1, w1, (pb - 256) * 8 + warp, lane, ed + 1 * 2048 * 32);
    } else if (pb < 768) {
        prep_node_pairs(src2, w2, (pb - 512) * 8 + warp, lane, ed + 2 * 2048 * 32);
    } else {  // 64 blocks x 8 warps = 512 nodes
        prep_node_pairs(src3, w3, (pb - 768) * 8 + warp, lane, ed + 3 * 2048 * 32);
    }
}

// ---------------------------------------------------------------------------
// Direct-gather layer kernel. Warp = (node, 256-col group); lane covers
// 8 fp16 cols via one LDG.128 per edge. 64 edges = 32 pair records.
// ---------------------------------------------------------------------------
template <bool RELU, bool FINAL>
__global__ __launch_bounds__(256)
void layer_direct(const __half* __restrict__ h_in,
                  const int4*  __restrict__ pairs,
                  const float* __restrict__ bias,
                  void*        __restrict__ outv,
                  int nodes) {
    const int wg   = (blockIdx.x * blockDim.x + threadIdx.x) >> 5;
    const int lane = threadIdx.x & 31;
    const int node = wg >> 1;
    const int grp  = wg & 1;                    // which 256-col half of the batch
    if (node >= nodes) return;

    // byte base: col = grp*256 + lane*8 (fp16) -> bytes = grp*512 + lane*16
    const char* hb = (const char*)h_in + grp * 512 + lane * 16;
    const int4* ep = pairs + node * 32;

    float a0 = 0.f, a1 = 0.f, a2 = 0.f, a3 = 0.f;
    float a4 = 0.f, a5 = 0.f, a6 = 0.f, a7 = 0.f;

#pragma unroll 4
    for (int k = 0; k < 32; k++) {
        int4 e = __ldg(ep + k);
        uint4 g0 = __ldg((const uint4*)(hb + e.x));   // 8 cols of source row 0
        uint4 g1 = __ldg((const uint4*)(hb + e.z));   // 8 cols of source row 1
        float w0 = __int_as_float(e.y);
        float w1 = __int_as_float(e.w);
        float2 t;
        t = __half22float2(*(__half2*)&g0.x); a0 = fmaf(t.x, w0, a0); a1 = fmaf(t.y, w0, a1);
        t = __half22float2(*(__half2*)&g0.y); a2 = fmaf(t.x, w0, a2); a3 = fmaf(t.y, w0, a3);
        t = __half22float2(*(__half2*)&g0.z); a4 = fmaf(t.x, w0, a4); a5 = fmaf(t.y, w0, a5);
        t = __half22float2(*(__half2*)&g0.w); a6 = fmaf(t.x, w0, a6); a7 = fmaf(t.y, w0, a7);
        t = __half22float2(*(__half2*)&g1.x); a0 = fmaf(t.x, w1, a0); a1 = fmaf(t.y, w1, a1);
        t = __half22float2(*(__half2*)&g1.y); a2 = fmaf(t.x, w1, a2); a3 = fmaf(t.y, w1, a3);
        t = __half22float2(*(__half2*)&g1.z); a4 = fmaf(t.x, w1, a4); a5 = fmaf(t.y, w1, a5);
        t = __half22float2(*(__half2*)&g1.w); a6 = fmaf(t.x, w1, a6); a7 = fmaf(t.y, w1, a7);
    }

    float bv = bias[node];
    float v0 = a0 + bv, v1 = a1 + bv, v2 = a2 + bv, v3 = a3 + bv;
    float v4 = a4 + bv, v5 = a5 + bv, v6 = a6 + bv, v7 = a7 + bv;
    if (RELU) {
        v0 = fmaxf(v0, 0.f); v1 = fmaxf(v1, 0.f); v2 = fmaxf(v2, 0.f); v3 = fmaxf(v3, 0.f);
        v4 = fmaxf(v4, 0.f); v5 = fmaxf(v5, 0.f); v6 = fmaxf(v6, 0.f); v7 = fmaxf(v7, 0.f);
    }

    if (!FINAL) {
        __half2 h0 = __floats2half2_rn(v0, v1);
        __half2 h1 = __floats2half2_rn(v2, v3);
        __half2 h2 = __floats2half2_rn(v4, v5);
        __half2 h3 = __floats2half2_rn(v6, v7);
        uint4 pk = make_uint4(*(unsigned*)&h0, *(unsigned*)&h1,
                              *(unsigned*)&h2, *(unsigned*)&h3);
        __half* out = (__half*)outv;
        *(uint4*)(out + (size_t)node * BATCH + grp * 256 + lane * 8) = pk;
    } else {
        // d_out [B, 512] fp32 row-major: out[col * 512 + node]
        float* out = (float*)outv;
        int c = grp * 256 + lane * 8;
        out[(size_t)(c + 0) * 512 + node] = v0;
        out[(size_t)(c + 1) * 512 + node] = v1;
        out[(size_t)(c + 2) * 512 + node] = v2;
        out[(size_t)(c + 3) * 512 + node] = v3;
        out[(size_t)(c + 4) * 512 + node] = v4;
        out[(size_t)(c + 5) * 512 + node] = v5;
        out[(size_t)(c + 6) * 512 + node] = v6;
        out[(size_t)(c + 7) * 512 + node] = v7;
    }
}

// ---------------------------------------------------------------------------
// Host launch
// ---------------------------------------------------------------------------
extern "C" void kernel_launch(void* const* d_in, const int* in_sizes, int n_in,
                              void* d_out, int out_size) {
    (void)n_in; (void)out_size;

    const float* x;
    const float* w[4];
    const float* b[4];
    const int*   src[4];

    if (in_sizes[0] == 2048) {
        // alphabetical metadata order: b0..b3, dst0..dst3, src0..src3, w0..w3, x
        for (int l = 0; l < 4; l++) {
            b[l]   = (const float*)d_in[l];
            src[l] = (const int*)d_in[8 + l];
            w[l]   = (const float*)d_in[12 + l];
        }
        x = (const float*)d_in[16];
    } else if (in_sizes[7] == 32768) {
        // reference-signature order: x, w0,b0, ..., w3,b3, src0,dst0, ...
        x = (const float*)d_in[0];
        for (int l = 0; l < 4; l++) {
            w[l]   = (const float*)d_in[1 + 2 * l];
            b[l]   = (const float*)d_in[2 + 2 * l];
            src[l] = (const int*)d_in[9 + 2 * l];
        }
    } else {
        // setup_inputs dict order: x, (w,b,src,dst) per layer
        x = (const float*)d_in[0];
        for (int l = 0; l < 4; l++) {
            w[l]   = (const float*)d_in[1 + 4 * l];
            b[l]   = (const float*)d_in[2 + 4 * l];
            src[l] = (const int*)d_in[3 + 4 * l];
        }
    }

    __half* hA; __half* hB; int4* ed;
    cudaGetSymbolAddress((void**)&hA, g_hA);
    cudaGetSymbolAddress((void**)&hB, g_hB);
    cudaGetSymbolAddress((void**)&ed, g_pairs);

    // 1) fused: transpose x -> hA (fp16) + pack edge pairs for all layers
    fused_prep<<<1088, 256>>>(x, hA,
                              src[0], w[0], src[1], w[1],
                              src[2], w[2], src[3], w[3],
                              ed);

    // 2) layers (n_prev: 512, 2048, 2048, 2048).
    //    Wide layers: 2048 nodes x 2 col-groups = 4096 warps = 512 CTAs.
    //    Final: 512 nodes x 2 groups = 1024 warps = 128 CTAs.
    layer_direct<true, false><<<512, 256>>>(hA, ed + 0 * 2048 * 32, b[0], hB, 2048);
    layer_direct<true, false><<<512, 256>>>(hB, ed + 1 * 2048 * 32, b[1], hA, 2048);
    layer_direct<true, false><<<512, 256>>>(hA, ed + 2 * 2048 * 32, b[2], hB, 2048);
    layer_direct<false, true><<<128, 256>>>(hB, ed + 3 * 2048 * 32, b[3], d_out, 512);
}

// round 13
// speedup vs baseline: 1.8630x; 1.1891x over previous
#include <cuda_runtime.h>
#include <cuda_fp16.h>
#include <cstdint>

// ---------------------------------------------------------------------------
// GraphNeuralNetwork: 4 sparse layers, DEG=64 parents per node, B=512.
// Round 13 (= R12 resubmit; prior run died to a container infra failure):
// direct-L2 gather with 2-warp edge split per (node, 256-col group)
// -> 8192 warps/big layer (occ ~85%) to cover L2 latency. Partials combined
// via SMEM. fp16 h [node,batch], fp32 weights + accumulation.
// ---------------------------------------------------------------------------

#define BATCH 512

__device__ __align__(16) __half g_hA[2048 * 512];
__device__ __align__(16) __half g_hB[2048 * 512];
__device__ __align__(16) int4   g_pairs[4][2048 * 32];  // {off0, w0, off1, w1} per edge pair

// ---------------------------------------------------------------------------
// Fused prep: transpose x (blocks 0..255) + pack edge pairs for all layers.
// offset = src * 1024 (byte offset of row in fp16 [node,batch] buffer).
// ---------------------------------------------------------------------------
__device__ __forceinline__ void prep_node_pairs(
    const int* __restrict__ src, const float* __restrict__ w,
    int gw, int lane, int4* __restrict__ ed) {
    int i0 = gw * 64 + 2 * lane;
    int   s0 = src[i0],     s1 = src[i0 + 1];
    float v0 = w[i0];       float v1 = w[i0 + 1];
    ed[gw * 32 + lane] = make_int4(s0 << 10, __float_as_int(v0),
                                   s1 << 10, __float_as_int(v1));
}

__global__ void fused_prep(
    const float* __restrict__ x, __half* __restrict__ hA,
    const int* __restrict__ src0, const float* __restrict__ w0,
    const int* __restrict__ src1, const float* __restrict__ w1,
    const int* __restrict__ src2, const float* __restrict__ w2,
    const int* __restrict__ src3, const float* __restrict__ w3,
    int4* __restrict__ ed) {
    __shared__ float t[32][33];
    int b   = blockIdx.x;
    int tid = threadIdx.x;

    if (b < 256) {
        // transpose x [512,512] fp32 -> hA [node, batch] fp16
        int bx = (b & 15) * 32, by = (b >> 4) * 32;
        int tx = tid & 31, ty = tid >> 5;       // 32 x 8
#pragma unroll
        for (int i = 0; i < 32; i += 8)
            t[ty + i][tx] = x[(by + ty + i) * 512 + bx + tx];
        __syncthreads();
#pragma unroll
        for (int i = 0; i < 32; i += 8)
            hA[(bx + ty + i) * 512 + by + tx] = __float2half(t[tx][ty + i]);
        return;
    }

    int lane = tid & 31;
    int warp = tid >> 5;                        // 8 warps/block -> 8 nodes/block
    int pb   = b - 256;
    if (pb < 256) {
        prep_node_pairs(src0, w0, pb * 8 + warp, lane, ed);
    } else if (pb < 512) {
        prep_node_pairs(src1, w1, (pb - 256) * 8 + warp, lane, ed + 1 * 2048 * 32);
    } else if (pb < 768) {
        prep_node_pairs(src2, w2, (pb - 512) * 8 + warp, lane, ed + 2 * 2048 * 32);
    } else {  // 64 blocks x 8 warps = 512 nodes
        prep_node_pairs(src3, w3, (pb - 768) * 8 + warp, lane, ed + 3 * 2048 * 32);
    }
}

// ---------------------------------------------------------------------------
// Direct-gather layer kernel, 2-warp split.
// Global warp wg: node = wg>>2, grp = (wg>>1)&1, half = wg&1.
// Each warp gathers 32 edges (16 pair records) with coalesced LDG.128.
// half=1 stores partials to SMEM; half=0 combines, adds bias, writes.
// Grid covers warps exactly: grid.x = nodes/2, 256 threads (8 warps).
// ---------------------------------------------------------------------------
template <bool RELU, bool FINAL>
__global__ __launch_bounds__(256)
void layer_direct(const __half* __restrict__ h_in,
                  const int4*  __restrict__ pairs,
                  const float* __restrict__ bias,
                  void*        __restrict__ outv) {
    __shared__ float sPart[4][256];             // [unit][i*32 + lane]

    const int tid   = threadIdx.x;
    const int lane  = tid & 31;
    const int wInB  = tid >> 5;                 // 0..7
    const int wg    = blockIdx.x * 8 + wInB;
    const int half  = wg & 1;
    const int grp   = (wg >> 1) & 1;
    const int node  = wg >> 2;
    const int unit  = wInB >> 1;                // 0..3 within block

    // byte base: col = grp*256 + lane*8 (fp16) -> bytes = grp*512 + lane*16
    const char* hb = (const char*)h_in + grp * 512 + lane * 16;
    const int4* ep = pairs + node * 32 + half * 16;

    float a0 = 0.f, a1 = 0.f, a2 = 0.f, a3 = 0.f;
    float a4 = 0.f, a5 = 0.f, a6 = 0.f, a7 = 0.f;

#pragma unroll
    for (int k = 0; k < 16; k++) {
        int4 e = __ldg(ep + k);
        uint4 g0 = __ldg((const uint4*)(hb + e.x));   // 8 cols of source row 0
        uint4 g1 = __ldg((const uint4*)(hb + e.z));   // 8 cols of source row 1
        float w0 = __int_as_float(e.y);
        float w1 = __int_as_float(e.w);
        float2 t;
        t = __half22float2(*(__half2*)&g0.x); a0 = fmaf(t.x, w0, a0); a1 = fmaf(t.y, w0, a1);
        t = __half22float2(*(__half2*)&g0.y); a2 = fmaf(t.x, w0, a2); a3 = fmaf(t.y, w0, a3);
        t = __half22float2(*(__half2*)&g0.z); a4 = fmaf(t.x, w0, a4); a5 = fmaf(t.y, w0, a5);
        t = __half22float2(*(__half2*)&g0.w); a6 = fmaf(t.x, w0, a6); a7 = fmaf(t.y, w0, a7);
        t = __half22float2(*(__half2*)&g1.x); a0 = fmaf(t.x, w1, a0); a1 = fmaf(t.y, w1, a1);
        t = __half22float2(*(__half2*)&g1.y); a2 = fmaf(t.x, w1, a2); a3 = fmaf(t.y, w1, a3);
        t = __half22float2(*(__half2*)&g1.z); a4 = fmaf(t.x, w1, a4); a5 = fmaf(t.y, w1, a5);
        t = __half22float2(*(__half2*)&g1.w); a6 = fmaf(t.x, w1, a6); a7 = fmaf(t.y, w1, a7);
    }

    if (half == 1) {                            // odd warp: publish partials
        sPart[unit][0 * 32 + lane] = a0;
        sPart[unit][1 * 32 + lane] = a1;
        sPart[unit][2 * 32 + lane] = a2;
        sPart[unit][3 * 32 + lane] = a3;
        sPart[unit][4 * 32 + lane] = a4;
        sPart[unit][5 * 32 + lane] = a5;
        sPart[unit][6 * 32 + lane] = a6;
        sPart[unit][7 * 32 + lane] = a7;
    }
    __syncthreads();
    if (half == 1) return;

    a0 += sPart[unit][0 * 32 + lane];
    a1 += sPart[unit][1 * 32 + lane];
    a2 += sPart[unit][2 * 32 + lane];
    a3 += sPart[unit][3 * 32 + lane];
    a4 += sPart[unit][4 * 32 + lane];
    a5 += sPart[unit][5 * 32 + lane];
    a6 += sPart[unit][6 * 32 + lane];
    a7 += sPart[unit][7 * 32 + lane];

    float bv = bias[node];
    float v0 = a0 + bv, v1 = a1 + bv, v2 = a2 + bv, v3 = a3 + bv;
    float v4 = a4 + bv, v5 = a5 + bv, v6 = a6 + bv, v7 = a7 + bv;
    if (RELU) {
        v0 = fmaxf(v0, 0.f); v1 = fmaxf(v1, 0.f); v2 = fmaxf(v2, 0.f); v3 = fmaxf(v3, 0.f);
        v4 = fmaxf(v4, 0.f); v5 = fmaxf(v5, 0.f); v6 = fmaxf(v6, 0.f); v7 = fmaxf(v7, 0.f);
    }

    if (!FINAL) {
        __half2 h0 = __floats2half2_rn(v0, v1);
        __half2 h1 = __floats2half2_rn(v2, v3);
        __half2 h2 = __floats2half2_rn(v4, v5);
        __half2 h3 = __floats2half2_rn(v6, v7);
        uint4 pk = make_uint4(*(unsigned*)&h0, *(unsigned*)&h1,
                              *(unsigned*)&h2, *(unsigned*)&h3);
        __half* out = (__half*)outv;
        *(uint4*)(out + (size_t)node * BATCH + grp * 256 + lane * 8) = pk;
    } else {
        // d_out [B, 512] fp32 row-major: out[col * 512 + node]
        float* out = (float*)outv;
        int c = grp * 256 + lane * 8;
        out[(size_t)(c + 0) * 512 + node] = v0;
        out[(size_t)(c + 1) * 512 + node] = v1;
        out[(size_t)(c + 2) * 512 + node] = v2;
        out[(size_t)(c + 3) * 512 + node] = v3;
        out[(size_t)(c + 4) * 512 + node] = v4;
        out[(size_t)(c + 5) * 512 + node] = v5;
        out[(size_t)(c + 6) * 512 + node] = v6;
        out[(size_t)(c + 7) * 512 + node] = v7;
    }
}

// ---------------------------------------------------------------------------
// Host launch
// ---------------------------------------------------------------------------
extern "C" void kernel_launch(void* const* d_in, const int* in_sizes, int n_in,
                              void* d_out, int out_size) {
    (void)n_in; (void)out_size;

    const float* x;
    const float* w[4];
    const float* b[4];
    const int*   src[4];

    if (in_sizes[0] == 2048) {
        // alphabetical metadata order: b0..b3, dst0..dst3, src0..src3, w0..w3, x
        for (int l = 0; l < 4; l++) {
            b[l]   = (const float*)d_in[l];
            src[l] = (const int*)d_in[8 + l];
            w[l]   = (const float*)d_in[12 + l];
        }
        x = (const float*)d_in[16];
    } else if (in_sizes[7] == 32768) {
        // reference-signature order: x, w0,b0, ..., w3,b3, src0,dst0, ...
        x = (const float*)d_in[0];
        for (int l = 0; l < 4; l++) {
            w[l]   = (const float*)d_in[1 + 2 * l];
            b[l]   = (const float*)d_in[2 + 2 * l];
            src[l] = (const int*)d_in[9 + 2 * l];
        }
    } else {
        // setup_inputs dict order: x, (w,b,src,dst) per layer
        x = (const float*)d_in[0];
        for (int l = 0; l < 4; l++) {
            w[l]   = (const float*)d_in[1 + 4 * l];
            b[l]   = (const float*)d_in[2 + 4 * l];
            src[l] = (const int*)d_in[3 + 4 * l];
        }
    }

    __half* hA; __half* hB; int4* ed;
    cudaGetSymbolAddress((void**)&hA, g_hA);
    cudaGetSymbolAddress((void**)&hB, g_hB);
    cudaGetSymbolAddress((void**)&ed, g_pairs);

    // 1) fused: transpose x -> hA (fp16) + pack edge pairs for all layers
    fused_prep<<<1088, 256>>>(x, hA,
                              src[0], w[0], src[1], w[1],
                              src[2], w[2], src[3], w[3],
                              ed);

    // 2) layers. Warps = nodes*4 (node x 2 col-groups x 2 edge-halves);
    //    grid.x = nodes/2 CTAs of 256 threads covers them exactly.
    layer_direct<true, false><<<1024, 256>>>(hA, ed + 0 * 2048 * 32, b[0], hB);
    layer_direct<true, false><<<1024, 256>>>(hB, ed + 1 * 2048 * 32, b[1], hA);
    layer_direct<true, false><<<1024, 256>>>(hA, ed + 2 * 2048 * 32, b[2], hB);
    layer_direct<false, true><<<256, 256>>>(hB, ed + 3 * 2048 * 32, b[3], d_out);
}

// round 14
// speedup vs baseline: 1.9532x; 1.0484x over previous
#include <cuda_runtime.h>
#include <cuda_fp16.h>
#include <cstdint>

// ---------------------------------------------------------------------------
// GraphNeuralNetwork: 4 sparse layers, DEG=64 parents per node, B=512.
// Round 14: direct-L2 gather, 4-warp edge split per (node, 256-col group).
// CTA = 1 node (8 warps = 2 col-groups x 4 edge-quarters); 16384 warps per
// big layer -> occ ~95% to cover L2 latency. Partials combined via SMEM.
// fp16 h [node,batch], fp32 weights + accumulation.
// ---------------------------------------------------------------------------

#define BATCH 512

__device__ __align__(16) __half g_hA[2048 * 512];
__device__ __align__(16) __half g_hB[2048 * 512];
__device__ __align__(16) int4   g_pairs[4][2048 * 32];  // {off0, w0, off1, w1} per edge pair

// ---------------------------------------------------------------------------
// Fused prep: transpose x (blocks 0..255) + pack edge pairs for all layers.
// offset = src * 1024 (byte offset of row in fp16 [node,batch] buffer).
// ---------------------------------------------------------------------------
__device__ __forceinline__ void prep_node_pairs(
    const int* __restrict__ src, const float* __restrict__ w,
    int gw, int lane, int4* __restrict__ ed) {
    int i0 = gw * 64 + 2 * lane;
    int   s0 = src[i0],     s1 = src[i0 + 1];
    float v0 = w[i0];       float v1 = w[i0 + 1];
    ed[gw * 32 + lane] = make_int4(s0 << 10, __float_as_int(v0),
                                   s1 << 10, __float_as_int(v1));
}

__global__ void fused_prep(
    const float* __restrict__ x, __half* __restrict__ hA,
    const int* __restrict__ src0, const float* __restrict__ w0,
    const int* __restrict__ src1, const float* __restrict__ w1,
    const int* __restrict__ src2, const float* __restrict__ w2,
    const int* __restrict__ src3, const float* __restrict__ w3,
    int4* __restrict__ ed) {
    __shared__ float t[32][33];
    int b   = blockIdx.x;
    int tid = threadIdx.x;

    if (b < 256) {
        // transpose x [512,512] fp32 -> hA [node, batch] fp16
        int bx = (b & 15) * 32, by = (b >> 4) * 32;
        int tx = tid & 31, ty = tid >> 5;       // 32 x 8
#pragma unroll
        for (int i = 0; i < 32; i += 8)
            t[ty + i][tx] = x[(by + ty + i) * 512 + bx + tx];
        __syncthreads();
#pragma unroll
        for (int i = 0; i < 32; i += 8)
            hA[(bx + ty + i) * 512 + by + tx] = __float2half(t[tx][ty + i]);
        return;
    }

    int lane = tid & 31;
    int warp = tid >> 5;                        // 8 warps/block -> 8 nodes/block
    int pb   = b - 256;
    if (pb < 256) {
        prep_node_pairs(src0, w0, pb * 8 + warp, lane, ed);
    } else if (pb < 512) {
        prep_node_pairs(src1, w1, (pb - 256) * 8 + warp, lane, ed + 1 * 2048 * 32);
    } else if (pb < 768) {
        prep_node_pairs(src2, w2, (pb - 512) * 8 + warp, lane, ed + 2 * 2048 * 32);
    } else {  // 64 blocks x 8 warps = 512 nodes
        prep_node_pairs(src3, w3, (pb - 768) * 8 + warp, lane, ed + 3 * 2048 * 32);
    }
}

// ---------------------------------------------------------------------------
// Direct-gather layer kernel, 4-warp split. CTA = 1 node, 8 warps:
//   warp w: grp = w>>2 (256-col half of batch), half = w&3 (16-edge quarter).
// Each warp gathers 16 edges (8 pair records) with coalesced LDG.128.
// Halves 1-3 publish partials to SMEM; half 0 combines, + bias, writes.
// ---------------------------------------------------------------------------
template <bool RELU, bool FINAL>
__global__ __launch_bounds__(256)
void layer_direct(const __half* __restrict__ h_in,
                  const int4*  __restrict__ pairs,
                  const float* __restrict__ bias,
                  void*        __restrict__ outv) {
    __shared__ float sPart[2][3][256];          // [grp][half-1][i*32 + lane]

    const int tid   = threadIdx.x;
    const int lane  = tid & 31;
    const int wInB  = tid >> 5;                 // 0..7
    const int half  = wInB & 3;
    const int grp   = wInB >> 2;                // 0/1
    const int node  = blockIdx.x;

    // byte base: col = grp*256 + lane*8 (fp16) -> bytes = grp*512 + lane*16
    const char* hb = (const char*)h_in + grp * 512 + lane * 16;
    const int4* ep = pairs + node * 32 + half * 8;

    float a0 = 0.f, a1 = 0.f, a2 = 0.f, a3 = 0.f;
    float a4 = 0.f, a5 = 0.f, a6 = 0.f, a7 = 0.f;

#pragma unroll
    for (int k = 0; k < 8; k++) {
        int4 e = __ldg(ep + k);
        uint4 g0 = __ldg((const uint4*)(hb + e.x));   // 8 cols of source row 0
        uint4 g1 = __ldg((const uint4*)(hb + e.z));   // 8 cols of source row 1
        float w0 = __int_as_float(e.y);
        float w1 = __int_as_float(e.w);
        float2 t;
        t = __half22float2(*(__half2*)&g0.x); a0 = fmaf(t.x, w0, a0); a1 = fmaf(t.y, w0, a1);
        t = __half22float2(*(__half2*)&g0.y); a2 = fmaf(t.x, w0, a2); a3 = fmaf(t.y, w0, a3);
        t = __half22float2(*(__half2*)&g0.z); a4 = fmaf(t.x, w0, a4); a5 = fmaf(t.y, w0, a5);
        t = __half22float2(*(__half2*)&g0.w); a6 = fmaf(t.x, w0, a6); a7 = fmaf(t.y, w0, a7);
        t = __half22float2(*(__half2*)&g1.x); a0 = fmaf(t.x, w1, a0); a1 = fmaf(t.y, w1, a1);
        t = __half22float2(*(__half2*)&g1.y); a2 = fmaf(t.x, w1, a2); a3 = fmaf(t.y, w1, a3);
        t = __half22float2(*(__half2*)&g1.z); a4 = fmaf(t.x, w1, a4); a5 = fmaf(t.y, w1, a5);
        t = __half22float2(*(__half2*)&g1.w); a6 = fmaf(t.x, w1, a6); a7 = fmaf(t.y, w1, a7);
    }

    if (half != 0) {                            // warps 1-3 of each grp: publish
        float* sp = sPart[grp][half - 1];
        sp[0 * 32 + lane] = a0;
        sp[1 * 32 + lane] = a1;
        sp[2 * 32 + lane] = a2;
        sp[3 * 32 + lane] = a3;
        sp[4 * 32 + lane] = a4;
        sp[5 * 32 + lane] = a5;
        sp[6 * 32 + lane] = a6;
        sp[7 * 32 + lane] = a7;
    }
    __syncthreads();
    if (half != 0) return;

#pragma unroll
    for (int h = 0; h < 3; h++) {
        const float* sp = sPart[grp][h];
        a0 += sp[0 * 32 + lane];
        a1 += sp[1 * 32 + lane];
        a2 += sp[2 * 32 + lane];
        a3 += sp[3 * 32 + lane];
        a4 += sp[4 * 32 + lane];
        a5 += sp[5 * 32 + lane];
        a6 += sp[6 * 32 + lane];
        a7 += sp[7 * 32 + lane];
    }

    float bv = bias[node];
    float v0 = a0 + bv, v1 = a1 + bv, v2 = a2 + bv, v3 = a3 + bv;
    float v4 = a4 + bv, v5 = a5 + bv, v6 = a6 + bv, v7 = a7 + bv;
    if (RELU) {
        v0 = fmaxf(v0, 0.f); v1 = fmaxf(v1, 0.f); v2 = fmaxf(v2, 0.f); v3 = fmaxf(v3, 0.f);
        v4 = fmaxf(v4, 0.f); v5 = fmaxf(v5, 0.f); v6 = fmaxf(v6, 0.f); v7 = fmaxf(v7, 0.f);
    }

    if (!FINAL) {
        __half2 h0 = __floats2half2_rn(v0, v1);
        __half2 h1 = __floats2half2_rn(v2, v3);
        __half2 h2 = __floats2half2_rn(v4, v5);
        __half2 h3 = __floats2half2_rn(v6, v7);
        uint4 pk = make_uint4(*(unsigned*)&h0, *(unsigned*)&h1,
                              *(unsigned*)&h2, *(unsigned*)&h3);
        __half* out = (__half*)outv;
        *(uint4*)(out + (size_t)node * BATCH + grp * 256 + lane * 8) = pk;
    } else {
        // d_out [B, 512] fp32 row-major: out[col * 512 + node]
        float* out = (float*)outv;
        int c = grp * 256 + lane * 8;
        out[(size_t)(c + 0) * 512 + node] = v0;
        out[(size_t)(c + 1) * 512 + node] = v1;
        out[(size_t)(c + 2) * 512 + node] = v2;
        out[(size_t)(c + 3) * 512 + node] = v3;
        out[(size_t)(c + 4) * 512 + node] = v4;
        out[(size_t)(c + 5) * 512 + node] = v5;
        out[(size_t)(c + 6) * 512 + node] = v6;
        out[(size_t)(c + 7) * 512 + node] = v7;
    }
}

// ---------------------------------------------------------------------------
// Host launch
// ---------------------------------------------------------------------------
extern "C" void kernel_launch(void* const* d_in, const int* in_sizes, int n_in,
                              void* d_out, int out_size) {
    (void)n_in; (void)out_size;

    const float* x;
    const float* w[4];
    const float* b[4];
    const int*   src[4];

    if (in_sizes[0] == 2048) {
        // alphabetical metadata order: b0..b3, dst0..dst3, src0..src3, w0..w3, x
        for (int l = 0; l < 4; l++) {
            b[l]   = (const float*)d_in[l];
            src[l] = (const int*)d_in[8 + l];
            w[l]   = (const float*)d_in[12 + l];
        }
        x = (const float*)d_in[16];
    } else if (in_sizes[7] == 32768) {
        // reference-signature order: x, w0,b0, ..., w3,b3, src0,dst0, ...
        x = (const float*)d_in[0];
        for (int l = 0; l < 4; l++) {
            w[l]   = (const float*)d_in[1 + 2 * l];
            b[l]   = (const float*)d_in[2 + 2 * l];
            src[l] = (const int*)d_in[9 + 2 * l];
        }
    } else {
        // setup_inputs dict order: x, (w,b,src,dst) per layer
        x = (const float*)d_in[0];
        for (int l = 0; l < 4; l++) {
            w[l]   = (const float*)d_in[1 + 4 * l];
            b[l]   = (const float*)d_in[2 + 4 * l];
            src[l] = (const int*)d_in[3 + 4 * l];
        }
    }

    __half* hA; __half* hB; int4* ed;
    cudaGetSymbolAddress((void**)&hA, g_hA);
    cudaGetSymbolAddress((void**)&hB, g_hB);
    cudaGetSymbolAddress((void**)&ed, g_pairs);

    // 1) fused: transpose x -> hA (fp16) + pack edge pairs for all layers
    fused_prep<<<1088, 256>>>(x, hA,
                              src[0], w[0], src[1], w[1],
                              src[2], w[2], src[3], w[3],
                              ed);

    // 2) layers. CTA = 1 node (8 warps: 2 col-groups x 4 edge-quarters).
    layer_direct<true, false><<<2048, 256>>>(hA, ed + 0 * 2048 * 32, b[0], hB);
    layer_direct<true, false><<<2048, 256>>>(hB, ed + 1 * 2048 * 32, b[1], hA);
    layer_direct<true, false><<<2048, 256>>>(hA, ed + 2 * 2048 * 32, b[2], hB);
    layer_direct<false, true><<<512, 256>>>(hB, ed + 3 * 2048 * 32, b[3], d_out);
}